// round 6
// baseline (speedup 1.0000x reference)
#include <cuda_runtime.h>
#include <cstdint>

#define EPSBN 1e-5f
#define HH 300
#define WW 300
#define HW 90000
#define BB 4
#define QMAX 16256.f   // 127*128

// ===========================================================================
// PTX helpers — baseline instructions only (target is sm_103 without 'a')
// ===========================================================================
__device__ __forceinline__ uint32_t smem_u32(const void* p) {
    uint32_t a;
    asm("{ .reg .u64 t; cvta.to.shared.u64 t, %1; cvt.u32.u64 %0, t; }"
        : "=r"(a) : "l"(p));
    return a;
}
__device__ __forceinline__ void ldsm4(uint32_t* r, uint32_t addr) {
    asm volatile("ldmatrix.sync.aligned.m8n8.x4.shared.b16 {%0,%1,%2,%3}, [%4];"
                 : "=r"(r[0]), "=r"(r[1]), "=r"(r[2]), "=r"(r[3]) : "r"(addr));
}
__device__ __forceinline__ void mma_s8(int* c, const uint32_t* a,
                                       uint32_t b0, uint32_t b1) {
    asm volatile(
        "mma.sync.aligned.m16n8k32.row.col.s32.s8.s8.s32 "
        "{%0,%1,%2,%3}, {%4,%5,%6,%7}, {%8,%9}, {%0,%1,%2,%3};"
        : "+r"(c[0]), "+r"(c[1]), "+r"(c[2]), "+r"(c[3])
        : "r"(a[0]), "r"(a[1]), "r"(a[2]), "r"(a[3]), "r"(b0), "r"(b1));
}
#define CP_ASYNC16(dst, src) \
    asm volatile("cp.async.cg.shared.global [%0], [%1], 16;" :: "r"(dst), "l"(src))
#define CP_COMMIT() asm volatile("cp.async.commit_group;" ::: "memory")
#define CP_WAIT1()  asm volatile("cp.async.wait_group 1;" ::: "memory")
#define CP_WAIT0()  asm volatile("cp.async.wait_group 0;" ::: "memory")

// ===========================================================================
// Device scratch (allocation-guard-safe)
// ===========================================================================
__device__ unsigned g_absmax_u;
__device__ float g_sw_sh[64], g_sw_hm[64], g_sw_rg[64];
__device__ __align__(16) signed char g_a8h[(size_t)BB * HW * 256];
__device__ __align__(16) signed char g_a8l[(size_t)BB * HW * 256];
__device__ __align__(16) float g_trunkf[(size_t)BB * HW * 64];
__device__ __align__(16) signed char g_wimg_sh[36 * 10240];
__device__ __align__(16) signed char g_wimg_hm[9 * 10240];
__device__ __align__(16) signed char g_wimg_rg[9 * 10240];

__device__ __forceinline__ void quant15(float x, float inv,
                                        signed char& h, signed char& l) {
    float qf = fminf(fmaxf(x * inv, -QMAX), QMAX);
    int q = __float2int_rn(qf);
    int qh = __float2int_rn(qf * 0.0078125f);   // /128
    h = (signed char)qh;
    l = (signed char)(q - (qh << 7));
}

// ===========================================================================
// reset + global |max| of bev
// ===========================================================================
__global__ void reset_kernel() { g_absmax_u = 0u; }

__global__ __launch_bounds__(256) void maxabs_kernel(const float4* __restrict__ in, int n4)
{
    float m = 0.f;
    for (int i = blockIdx.x * 256 + threadIdx.x; i < n4; i += gridDim.x * 256) {
        float4 v = in[i];
        m = fmaxf(m, fmaxf(fmaxf(fabsf(v.x), fabsf(v.y)), fmaxf(fabsf(v.z), fabsf(v.w))));
    }
#pragma unroll
    for (int o = 16; o; o >>= 1) m = fmaxf(m, __shfl_xor_sync(~0u, m, o));
    __shared__ float s[8];
    if ((threadIdx.x & 31) == 0) s[threadIdx.x >> 5] = m;
    __syncthreads();
    if (threadIdx.x < 8) {
        m = s[threadIdx.x];
#pragma unroll
        for (int o = 4; o; o >>= 1) m = fmaxf(m, __shfl_xor_sync(0xffu, m, o));
        if (threadIdx.x == 0) atomicMax(&g_absmax_u, __float_as_uint(m));
    }
}

// ===========================================================================
// NCHW fp32 -> NHWC int8 hi/lo limbs (bev), per-tensor scale
// ===========================================================================
__global__ __launch_bounds__(256) void nhwcq_kernel(const float* __restrict__ in)
{
    __shared__ float tile[32][33];
    const float inv = QMAX / fmaxf(__uint_as_float(g_absmax_u), 1e-20f);
    const int tx = threadIdx.x & 31, ty = threadIdx.x >> 5;
    const int w0 = blockIdx.x * 32, c0 = blockIdx.y * 32;
    const int b = blockIdx.z / HH, h = blockIdx.z % HH;
#pragma unroll
    for (int q = 0; q < 4; q++) {
        int c = c0 + ty * 4 + q, w = w0 + tx;
        tile[ty * 4 + q][tx] = (w < WW) ? in[(((size_t)b * 256 + c) * HH + h) * WW + w] : 0.f;
    }
    __syncthreads();
#pragma unroll
    for (int q = 0; q < 4; q++) {
        int w = w0 + ty * 4 + q;
        if (w >= WW) continue;
        signed char qh, ql;
        quant15(tile[tx][ty * 4 + q], inv, qh, ql);
        size_t o = ((size_t)b * HW + (size_t)h * WW + w) * 256 + c0 + tx;
        g_a8h[o] = qh;
        g_a8l[o] = ql;
    }
}

// ===========================================================================
// Weight prep: per-oc max -> scale; quantize to limbs in per (cchunk, shift)
// B images: [64 n][pitch 80] s8, hi at +0, lo at +5120 (10240 B per image)
// ===========================================================================
__global__ __launch_bounds__(256) void prep_w_kernel(
    const float* __restrict__ w, signed char* __restrict__ dst,
    float* __restrict__ swout, int CIN)
{
    __shared__ float s_red[8];
    __shared__ float s_inv;
    const int oc = blockIdx.x;
    const int n = CIN * 9;
    const float* wo = w + (size_t)oc * n;

    float m = 0.f;
    for (int i = threadIdx.x; i < n; i += 256) m = fmaxf(m, fabsf(wo[i]));
#pragma unroll
    for (int o = 16; o; o >>= 1) m = fmaxf(m, __shfl_xor_sync(~0u, m, o));
    if ((threadIdx.x & 31) == 0) s_red[threadIdx.x >> 5] = m;
    __syncthreads();
    if (threadIdx.x == 0) {
        float mm = 0.f;
#pragma unroll
        for (int i = 0; i < 8; i++) mm = fmaxf(mm, s_red[i]);
        mm = fmaxf(mm, 1e-20f);
        swout[oc] = mm / QMAX;
        s_inv = QMAX / mm;
    }
    __syncthreads();
    const float inv = s_inv;
    for (int i = threadIdx.x; i < n; i += 256) {
        int kk = i % 9, ci = i / 9;
        int cc = ci >> 6, c = ci & 63;
        signed char h, l;
        quant15(wo[i], inv, h, l);
        size_t base = (size_t)(cc * 9 + kk) * 10240;
        dst[base + oc * 80 + c] = h;
        dst[base + 5120 + oc * 80 + c] = l;
    }
}

// ===========================================================================
// conv3x3 via imma s8 two-limb (3 integer passes), BN + ReLU epilogue.
// CTA 256 thr (8 warps), tile 8 rows x 16 cols x 64 oc. Warp = one row, M=16.
// CCH=4 (trunk): A = bev limbs (per-tensor scale), out = fp32 NHWC.
// CCH=1 (head):  A = trunk fp32 (tile-local requant), out = 1x1+bias NCHW fp32.
// ===========================================================================
template <int CCH, int NOUT>
__global__ __launch_bounds__(256, 2) void conv_imma_kernel(
    const signed char* __restrict__ ah8, const signed char* __restrict__ al8,
    const float* __restrict__ actf,
    const signed char* __restrict__ wimg,
    const float* __restrict__ swsc,
    const float* __restrict__ gg, const float* __restrict__ bbp,
    const float* __restrict__ mm, const float* __restrict__ vv,
    const float* __restrict__ w2, const float* __restrict__ b2,
    float* __restrict__ out_trunk, float* __restrict__ out_head)
{
    constexpr int NSH = CCH * 9;

    extern __shared__ __align__(16) unsigned char dynsmem[];
    unsigned char* sB = dynsmem;                 // 2 x 10240 (double buffer)
    unsigned char* s_hh8 = dynsmem + 20480;      // 180 x 80
    unsigned char* s_hl8 = dynsmem + 34880;      // 180 x 80   (end 49280)
    float* s_scr = (float*)(dynsmem + 49280);    // heads only: 180*64 fp32
    float* s_mid_t = (float*)dynsmem;            // trunk epilogue alias (pitch 68)
    float* s_mid_h = (float*)(dynsmem + 49280);  // head epilogue alias (pitch 65)

    __shared__ float s_scale[64], s_shift[64], s_wsc[64];
    __shared__ float s_w2[(NOUT > 0 ? NOUT : 1) * 64];
    __shared__ float s_b2[(NOUT > 0 ? NOUT : 1)];
    __shared__ float s_red[8];
    __shared__ float s_tilescale, s_tileinv;

    const int tid = threadIdx.x;
    const int w = tid >> 5, lane = tid & 31;
    const int bx = blockIdx.x * 16, by = blockIdx.y * 8;
    const int b = blockIdx.z;

    if (tid < 64) {
        float sc = gg[tid] * rsqrtf(vv[tid] + EPSBN);
        s_scale[tid] = sc;
        s_shift[tid] = bbp[tid] - mm[tid] * sc;
        s_wsc[tid] = swsc[tid];
    }
    if (NOUT > 0) {
        for (int i = tid; i < NOUT * 64; i += 256) s_w2[i] = w2[i];
        if (tid < NOUT) s_b2[tid] = b2[tid];
    }

    const int mA = lane & 15;
    const int kselA = (lane >> 4) * 16;          // bytes
    const int oclB = (lane & 7) + ((lane >> 4) & 1) * 8;
    const int koffB = (lane & 8) ? 16 : 0;       // bytes

    const uint32_t sB_u = smem_u32(sB);
    const uint32_t shh_u = smem_u32(s_hh8);

    int p1[8][4], p23[8][4];
#pragma unroll
    for (int i = 0; i < 8; i++)
#pragma unroll
        for (int j = 0; j < 4; j++) { p1[i][j] = 0; p23[i][j] = 0; }

    // prefetch first B image (10240 B)
    {
        const char* src = (const char*)wimg;
        for (int i = tid; i < 640; i += 256)
            CP_ASYNC16(sB_u + i * 16, src + (size_t)i * 16);
        CP_COMMIT();
    }

    for (int cc = 0; cc < CCH; cc++) {
        __syncthreads();
        if (CCH > 1) {
            // ---- trunk halo: int8 limbs direct from gmem ----
            for (int idx = tid; idx < 180 * 4; idx += 256) {
                int pix = idx >> 2, j = idx & 3;
                int r = pix / 18, col = pix % 18;
                int gy = by - 1 + r, gx = bx - 1 + col;
                uint4 vh = make_uint4(0, 0, 0, 0), vl = make_uint4(0, 0, 0, 0);
                if ((unsigned)gy < HH && (unsigned)gx < WW) {
                    size_t e = ((size_t)b * HW + (size_t)gy * WW + gx) * 256 + cc * 64 + j * 16;
                    vh = *(const uint4*)(ah8 + e);
                    vl = *(const uint4*)(al8 + e);
                }
                *(uint4*)(s_hh8 + pix * 80 + j * 16) = vh;
                *(uint4*)(s_hl8 + pix * 80 + j * 16) = vl;
            }
        } else {
            // ---- head halo: fp32 -> tile-local quantization ----
            for (int idx = tid; idx < 180 * 16; idx += 256) {
                int pix = idx >> 4, j = idx & 15;
                int r = pix / 18, col = pix % 18;
                int gy = by - 1 + r, gx = bx - 1 + col;
                uint4 v = make_uint4(0, 0, 0, 0);
                if ((unsigned)gy < HH && (unsigned)gx < WW)
                    v = *(const uint4*)(actf + ((size_t)b * HW + (size_t)gy * WW + gx) * 64 + j * 4);
                *(uint4*)(s_scr + pix * 64 + j * 4) = v;
            }
            __syncthreads();
            float m = 0.f;
            for (int i = tid; i < 180 * 64; i += 256) m = fmaxf(m, fabsf(s_scr[i]));
#pragma unroll
            for (int o = 16; o; o >>= 1) m = fmaxf(m, __shfl_xor_sync(~0u, m, o));
            if (lane == 0) s_red[w] = m;
            __syncthreads();
            if (tid == 0) {
                float mm2 = 0.f;
#pragma unroll
                for (int i = 0; i < 8; i++) mm2 = fmaxf(mm2, s_red[i]);
                mm2 = fmaxf(mm2, 1e-20f);
                s_tilescale = mm2 / QMAX;
                s_tileinv = QMAX / mm2;
            }
            __syncthreads();
            const float inv = s_tileinv;
            for (int i = tid; i < 180 * 64; i += 256) {
                int pix = i >> 6, c = i & 63;
                signed char h, l;
                quant15(s_scr[i], inv, h, l);
                s_hh8[pix * 80 + c] = h;
                s_hl8[pix * 80 + c] = l;
            }
        }

#pragma unroll 1
        for (int k = 0; k < 9; k++) {
            const int s = cc * 9 + k;
            const uint32_t cur = (uint32_t)(s & 1);
            if (s + 1 < NSH) {
                const char* src = (const char*)(wimg + (size_t)(s + 1) * 10240);
                uint32_t dst = sB_u + (uint32_t)((s + 1) & 1) * 10240;
                for (int i = tid; i < 640; i += 256)
                    CP_ASYNC16(dst + i * 16, src + (size_t)i * 16);
                CP_COMMIT();
                CP_WAIT1();
            } else {
                CP_WAIT0();
            }
            __syncthreads();

            const int ky = k / 3, kx = k - 3 * ky;
            const uint32_t aBase = shh_u + (uint32_t)(((w + ky) * 18 + mA + kx) * 80 + kselA);
            const uint32_t bBase = sB_u + cur * 10240 + (uint32_t)(oclB * 80 + koffB);

#pragma unroll
            for (int kc = 0; kc < 2; kc++) {
                uint32_t ah[4], al[4];
                ldsm4(ah, aBase + kc * 32);
                ldsm4(al, aBase + 14400 + kc * 32);
#pragma unroll
                for (int pr = 0; pr < 4; pr++) {
                    uint32_t bh[4], bl[4];
                    ldsm4(bh, bBase + pr * 1280 + kc * 32);
                    ldsm4(bl, bBase + 5120 + pr * 1280 + kc * 32);
                    mma_s8(p1[2 * pr + 0], ah, bh[0], bh[1]);
                    mma_s8(p1[2 * pr + 1], ah, bh[2], bh[3]);
                    mma_s8(p23[2 * pr + 0], ah, bl[0], bl[1]);
                    mma_s8(p23[2 * pr + 1], ah, bl[2], bl[3]);
                    mma_s8(p23[2 * pr + 0], al, bh[0], bh[1]);
                    mma_s8(p23[2 * pr + 1], al, bh[2], bh[3]);
                }
            }
            __syncthreads();
        }
    }

    // ---- dequant + BN + ReLU ----
    const float s_a = (CCH > 1) ? (__uint_as_float(g_absmax_u) / QMAX) : s_tilescale;
    float v[8][4];
#pragma unroll
    for (int nt = 0; nt < 8; nt++)
#pragma unroll
        for (int cj = 0; cj < 4; cj++) {
            int oc = nt * 8 + (lane & 3) * 2 + (cj & 1);
            float val = s_a * s_wsc[oc] *
                        fmaf(16384.f, (float)p1[nt][cj], 128.f * (float)p23[nt][cj]);
            v[nt][cj] = fmaxf(val * s_scale[oc] + s_shift[oc], 0.f);
        }

    if (NOUT == 0) {
        // trunk: stage to smem (pitch 68 floats), then coalesced NHWC fp32 out
        __syncthreads();   // all mma/ldsm done; safe to alias sB/halo
#pragma unroll
        for (int side = 0; side < 2; side++) {
            int p = w * 16 + (lane >> 2) + side * 8;
            int oc0 = (lane & 3) * 2;
#pragma unroll
            for (int nt = 0; nt < 8; nt++) {
                float2 t = make_float2(v[nt][side * 2 + 0], v[nt][side * 2 + 1]);
                *(float2*)&s_mid_t[p * 68 + nt * 8 + oc0] = t;
            }
        }
        __syncthreads();
        for (int i = tid; i < 2048; i += 256) {
            int p = i >> 4, j = i & 15;
            int yy = by + (p >> 4), xx = bx + (p & 15);
            if (yy < HH && xx < WW) {
                uint4 t = *(uint4*)&s_mid_t[p * 68 + j * 4];
                *(uint4*)(out_trunk + ((size_t)b * HW + (size_t)yy * WW + xx) * 64 + j * 4) = t;
            }
        }
    } else {
        // head: stage mid, then fused 1x1 + bias -> NCHW fp32
        __syncthreads();
#pragma unroll
        for (int side = 0; side < 2; side++) {
            int p = w * 16 + (lane >> 2) + side * 8;
            int oc0 = (lane & 3) * 2;
#pragma unroll
            for (int nt = 0; nt < 8; nt++) {
                s_mid_h[p * 65 + nt * 8 + oc0] = v[nt][side * 2 + 0];
                s_mid_h[p * 65 + nt * 8 + oc0 + 1] = v[nt][side * 2 + 1];
            }
        }
        __syncthreads();
        if (tid < 128) {
            int p = tid;
            int yy = by + (p >> 4), xx = bx + (p & 15);
            if (yy < HH && xx < WW) {
                const float* row = s_mid_h + p * 65;
                float o[NOUT > 0 ? NOUT : 1];
#pragma unroll
                for (int n = 0; n < NOUT; n++) o[n] = s_b2[n];
#pragma unroll 8
                for (int c = 0; c < 64; c++) {
                    float a = row[c];
#pragma unroll
                    for (int n = 0; n < NOUT; n++) o[n] += a * s_w2[n * 64 + c];
                }
#pragma unroll
                for (int n = 0; n < NOUT; n++)
                    out_head[((size_t)(b * NOUT + n) * HH + yy) * WW + xx] = o[n];
            }
        }
    }
}

// ===========================================================================
extern "C" void kernel_launch(void* const* d_in, const int* in_sizes, int n_in,
                              void* d_out, int out_size)
{
    const float* bev   = (const float*)d_in[0];
    const float* w_sh  = (const float*)d_in[1];
    const float* g_sh  = (const float*)d_in[2];
    const float* b_sh  = (const float*)d_in[3];
    const float* m_sh  = (const float*)d_in[4];
    const float* v_sh  = (const float*)d_in[5];
    const float* w_hm1 = (const float*)d_in[6];
    const float* g_hm1 = (const float*)d_in[7];
    const float* b_hm1 = (const float*)d_in[8];
    const float* m_hm1 = (const float*)d_in[9];
    const float* v_hm1 = (const float*)d_in[10];
    const float* w_hm2 = (const float*)d_in[11];
    const float* b_hm2 = (const float*)d_in[12];
    const float* w_rg1 = (const float*)d_in[13];
    const float* g_rg1 = (const float*)d_in[14];
    const float* b_rg1 = (const float*)d_in[15];
    const float* m_rg1 = (const float*)d_in[16];
    const float* v_rg1 = (const float*)d_in[17];
    const float* w_rg2 = (const float*)d_in[18];
    const float* b_rg2 = (const float*)d_in[19];

    signed char *a8h, *a8l, *wi_sh, *wi_hm, *wi_rg;
    float *trunkf, *sw_sh, *sw_hm, *sw_rg;
    cudaGetSymbolAddress((void**)&a8h, g_a8h);
    cudaGetSymbolAddress((void**)&a8l, g_a8l);
    cudaGetSymbolAddress((void**)&trunkf, g_trunkf);
    cudaGetSymbolAddress((void**)&wi_sh, g_wimg_sh);
    cudaGetSymbolAddress((void**)&wi_hm, g_wimg_hm);
    cudaGetSymbolAddress((void**)&wi_rg, g_wimg_rg);
    cudaGetSymbolAddress((void**)&sw_sh, g_sw_sh);
    cudaGetSymbolAddress((void**)&sw_hm, g_sw_hm);
    cudaGetSymbolAddress((void**)&sw_rg, g_sw_rg);

    const int DSMEM_T = 49280;
    const int DSMEM_H = 49280 + 180 * 64 * 4;   // +46080 = 95360
    cudaFuncSetAttribute(conv_imma_kernel<4, 0>, cudaFuncAttributeMaxDynamicSharedMemorySize, DSMEM_T);
    cudaFuncSetAttribute(conv_imma_kernel<1, 3>, cudaFuncAttributeMaxDynamicSharedMemorySize, DSMEM_H);
    cudaFuncSetAttribute(conv_imma_kernel<1, 8>, cudaFuncAttributeMaxDynamicSharedMemorySize, DSMEM_H);

    // 1. per-tensor |max| of bev
    reset_kernel<<<1, 1>>>();
    maxabs_kernel<<<1024, 256>>>((const float4*)bev, BB * 256 * HW / 4);

    // 2. bev NCHW fp32 -> NHWC int8 limbs
    nhwcq_kernel<<<dim3(10, 8, BB * HH), 256>>>(bev);

    // 3. weight images (per-oc scale + limbs)
    prep_w_kernel<<<64, 256>>>(w_sh, wi_sh, sw_sh, 256);
    prep_w_kernel<<<64, 256>>>(w_hm1, wi_hm, sw_hm, 64);
    prep_w_kernel<<<64, 256>>>(w_rg1, wi_rg, sw_rg, 64);

    dim3 grid(19, 38, BB);   // 16x8 pixel tiles

    // 4. trunk conv -> fp32 NHWC
    conv_imma_kernel<4, 0><<<grid, 256, DSMEM_T>>>(
        a8h, a8l, nullptr, wi_sh, sw_sh, g_sh, b_sh, m_sh, v_sh,
        nullptr, nullptr, trunkf, nullptr);

    // 5. heads (tile-local requant, fused 1x1 -> d_out)
    float* out = (float*)d_out;
    conv_imma_kernel<1, 3><<<grid, 256, DSMEM_H>>>(
        nullptr, nullptr, trunkf, wi_hm, sw_hm, g_hm1, b_hm1, m_hm1, v_hm1,
        w_hm2, b_hm2, nullptr, out);
    conv_imma_kernel<1, 8><<<grid, 256, DSMEM_H>>>(
        nullptr, nullptr, trunkf, wi_rg, sw_rg, g_rg1, b_rg1, m_rg1, v_rg1,
        w_rg2, b_rg2, nullptr, out + (size_t)BB * 3 * HW);
}

// round 7
// speedup vs baseline: 3.2566x; 3.2566x over previous
#include <cuda_runtime.h>
#include <cuda_fp16.h>
#include <cstdint>

#define EPSBN 1e-5f
#define HH 300
#define WW 300
#define HW 90000
#define BB 4

// ===========================================================================
// PTX helpers — baseline instructions only (target is sm_103 without 'a')
// ===========================================================================
__device__ __forceinline__ uint32_t smem_u32(const void* p) {
    uint32_t a;
    asm("{ .reg .u64 t; cvta.to.shared.u64 t, %1; cvt.u32.u64 %0, t; }"
        : "=r"(a) : "l"(p));
    return a;
}
__device__ __forceinline__ void ldsm4(uint32_t* r, uint32_t addr) {
    asm volatile("ldmatrix.sync.aligned.m8n8.x4.shared.b16 {%0,%1,%2,%3}, [%4];"
                 : "=r"(r[0]), "=r"(r[1]), "=r"(r[2]), "=r"(r[3]) : "r"(addr));
}
__device__ __forceinline__ void mma_f16(float* c, const uint32_t* a,
                                        uint32_t b0, uint32_t b1) {
    asm volatile(
        "mma.sync.aligned.m16n8k16.row.col.f32.f16.f16.f32 "
        "{%0,%1,%2,%3}, {%4,%5,%6,%7}, {%8,%9}, {%0,%1,%2,%3};"
        : "+f"(c[0]), "+f"(c[1]), "+f"(c[2]), "+f"(c[3])
        : "r"(a[0]), "r"(a[1]), "r"(a[2]), "r"(a[3]), "r"(b0), "r"(b1));
}
#define CP_ASYNC16(dst, src) \
    asm volatile("cp.async.cg.shared.global [%0], [%1], 16;" :: "r"(dst), "l"(src))
#define CP_COMMIT() asm volatile("cp.async.commit_group;" ::: "memory")
#define CP_WAIT1()  asm volatile("cp.async.wait_group 1;" ::: "memory")
#define CP_WAIT0()  asm volatile("cp.async.wait_group 0;" ::: "memory")

// ===========================================================================
// Device scratch (allocation-guard-safe)
// ===========================================================================
__device__ __half g_bev_hi[(size_t)BB * HW * 256];
__device__ __half g_bev_lo[(size_t)BB * HW * 256];
__device__ __half g_tr_hi[(size_t)BB * HW * 64];
__device__ __half g_tr_lo[(size_t)BB * HW * 64];
__device__ __half g_wimg_sh[36 * 4608];  // trunk: 4 cch x 9 shifts, [64 oc][72]
__device__ __half g_wimg_hm[9 * 4608];
__device__ __half g_wimg_rg[9 * 4608];

// ===========================================================================
// NCHW fp32 -> NHWC fp16 hi/lo limbs (bev)
// ===========================================================================
__global__ __launch_bounds__(256) void nhwc_kernel(const float* __restrict__ in)
{
    __shared__ float tile[32][33];
    const int tx = threadIdx.x & 31, ty = threadIdx.x >> 5;
    const int w0 = blockIdx.x * 32, c0 = blockIdx.y * 32;
    const int b = blockIdx.z / HH, h = blockIdx.z % HH;
#pragma unroll
    for (int q = 0; q < 4; q++) {
        int c = c0 + ty * 4 + q, w = w0 + tx;
        tile[ty * 4 + q][tx] = (w < WW) ? in[(((size_t)b * 256 + c) * HH + h) * WW + w] : 0.f;
    }
    __syncthreads();
#pragma unroll
    for (int q = 0; q < 4; q++) {
        int w = w0 + ty * 4 + q;
        if (w >= WW) continue;
        float x = tile[tx][ty * 4 + q];
        __half hi = __float2half_rn(x);
        __half lo = __float2half_rn(x - __half2float(hi));
        size_t o = ((size_t)b * HW + (size_t)h * WW + w) * 256 + c0 + tx;
        g_bev_hi[o] = hi;
        g_bev_lo[o] = lo;
    }
}

// ===========================================================================
// Weight prep: w[oc][ci][3][3] fp32 -> per (cchunk, shift) [64 oc][72] fp16
// ===========================================================================
__global__ void prep_w_kernel(const float* __restrict__ w,
                              __half* __restrict__ dst, int CIN)
{
    int i = blockIdx.x * 256 + threadIdx.x;
    if (i >= 64 * CIN * 9) return;
    int kk = i % 9;
    int ci = (i / 9) % CIN;
    int oc = i / (9 * CIN);
    int cc = ci >> 6, c = ci & 63;
    size_t base = (size_t)(cc * 9 + kk) * 4608;
    dst[base + oc * 72 + c] = __float2half_rn(w[i]);
}

// ===========================================================================
// conv3x3 + BN + ReLU via mma.sync fp16, 2-pass A-limb split.
// CTA: 256 thr (8 warps). Tile: 8 rows x 16 cols x 64 oc. Warp w = row by+w,
// M = 16 x-pixels, N = 64 oc, K = 64ch per cchunk per shift.
// NOUT==0: trunk -> NHWC fp16 hi/lo.  NOUT>0: fused 1x1+bias -> NCHW fp32.
// ===========================================================================
template <int CCH, int NOUT>
__global__ __launch_bounds__(256, 2) void conv_mma_kernel(
    const __half* __restrict__ act_hi, const __half* __restrict__ act_lo,
    const __half* __restrict__ wimg,
    const float* __restrict__ gg, const float* __restrict__ bbp,
    const float* __restrict__ mm, const float* __restrict__ vv,
    const float* __restrict__ w2, const float* __restrict__ b2,
    __half* __restrict__ out_hi, __half* __restrict__ out_lo,
    float* __restrict__ outf)
{
    constexpr int CIN = CCH * 64;
    constexpr int NSH = CCH * 9;

    extern __shared__ __align__(16) unsigned char dynsmem[];
    __half* sB = (__half*)dynsmem;                  // 2 x 4608 elems (18432 B)
    __half* s_hh = (__half*)(dynsmem + 18432);      // 180*72 (25920 B)
    __half* s_hl = s_hh + 180 * 72;                 // ends at 70272
    float* s_mid = (float*)dynsmem;                 // epilogue alias (heads)

    __shared__ float s_scale[64], s_shift[64];
    __shared__ float s_w2[(NOUT > 0 ? NOUT : 1) * 64];
    __shared__ float s_b2[(NOUT > 0 ? NOUT : 1)];

    const int tid = threadIdx.x;
    const int w = tid >> 5, lane = tid & 31;
    const int bx = blockIdx.x * 16, by = blockIdx.y * 8;
    const int b = blockIdx.z;

    if (tid < 64) {
        float sc = gg[tid] * rsqrtf(vv[tid] + EPSBN);
        s_scale[tid] = sc;
        s_shift[tid] = bbp[tid] - mm[tid] * sc;
    }
    if (NOUT > 0) {
        for (int i = tid; i < NOUT * 64; i += 256) s_w2[i] = w2[i];
        if (tid < NOUT) s_b2[tid] = b2[tid];
    }

    // lane invariants
    const int mA = lane & 15;
    const int kselA = (lane >> 4) * 8;                      // elems
    const int oclB = (lane & 7) + ((lane >> 4) & 1) * 8;
    const int koffB = (lane & 8) ? 8 : 0;                   // elems

    const uint32_t sB_u = smem_u32(sB);
    const uint32_t shh_u = smem_u32(s_hh);

    float acc[8][4];
#pragma unroll
    for (int i = 0; i < 8; i++)
#pragma unroll
        for (int j = 0; j < 4; j++) acc[i][j] = 0.f;

    // prefetch first B image (9216 B)
    {
        const char* src = (const char*)wimg;
        for (int i = tid; i < 576; i += 256)
            CP_ASYNC16(sB_u + i * 16, src + (size_t)i * 16);
        CP_COMMIT();
    }

    for (int cc = 0; cc < CCH; cc++) {
        __syncthreads();   // halo reuse safe
        // stage halo: 180 px x 64ch hi+lo, pixel pitch 72 elems
        for (int idx = tid; idx < 180 * 8; idx += 256) {
            int pix = idx >> 3, j = idx & 7;
            int r = pix / 18, col = pix % 18;
            int gy = by - 1 + r, gx = bx - 1 + col;
            uint4 vh = make_uint4(0, 0, 0, 0), vl = make_uint4(0, 0, 0, 0);
            if ((unsigned)gy < HH && (unsigned)gx < WW) {
                size_t e = ((size_t)b * HW + (size_t)gy * WW + gx) * CIN + cc * 64;
                vh = ((const uint4*)(act_hi + e))[j];
                vl = ((const uint4*)(act_lo + e))[j];
            }
            ((uint4*)(s_hh + pix * 72))[j] = vh;
            ((uint4*)(s_hl + pix * 72))[j] = vl;
        }

#pragma unroll 1
        for (int k = 0; k < 9; k++) {
            const int s = cc * 9 + k;
            const uint32_t cur = (uint32_t)(s & 1);
            if (s + 1 < NSH) {
                const char* src = (const char*)(wimg + (size_t)(s + 1) * 4608);
                uint32_t dst = sB_u + (uint32_t)((s + 1) & 1) * 9216;
                for (int i = tid; i < 576; i += 256)
                    CP_ASYNC16(dst + i * 16, src + (size_t)i * 16);
                CP_COMMIT();
                CP_WAIT1();
            } else {
                CP_WAIT0();
            }
            __syncthreads();

            const int ky = k / 3, kx = k - 3 * ky;
            const uint32_t aH = shh_u + (uint32_t)((((w + ky) * 18 + mA + kx) * 72 + kselA) * 2);
            const uint32_t aL = aH + 180 * 72 * 2;
            const uint32_t bH = sB_u + cur * 9216 + (uint32_t)((oclB * 72 + koffB) * 2);

#pragma unroll
            for (int kc = 0; kc < 4; kc++) {
                uint32_t ah[4], al[4];
                ldsm4(ah, aH + kc * 32);
                ldsm4(al, aL + kc * 32);
#pragma unroll
                for (int ng = 0; ng < 4; ng++) {
                    uint32_t bh[4];
                    ldsm4(bh, bH + ng * 2304 + kc * 32);
                    mma_f16(acc[2 * ng + 0], ah, bh[0], bh[1]);
                    mma_f16(acc[2 * ng + 1], ah, bh[2], bh[3]);
                    mma_f16(acc[2 * ng + 0], al, bh[0], bh[1]);
                    mma_f16(acc[2 * ng + 1], al, bh[2], bh[3]);
                }
            }
            __syncthreads();   // protect sB[cur] + halo from next iteration
        }
    }

    // ---- epilogue: BN + ReLU ----
    // acc[nt][cj]: oc = nt*8 + (lane&3)*2 + (cj&1); m = (lane>>2) + (cj>>1)*8
#pragma unroll
    for (int nt = 0; nt < 8; nt++)
#pragma unroll
        for (int cj = 0; cj < 4; cj++) {
            int oc = nt * 8 + (lane & 3) * 2 + (cj & 1);
            acc[nt][cj] = fmaxf(acc[nt][cj] * s_scale[oc] + s_shift[oc], 0.f);
        }

    const int y = by + w;

    if (NOUT == 0) {
        // trunk: write NHWC fp16 hi/lo pairs
#pragma unroll
        for (int side = 0; side < 2; side++) {
            int m = (lane >> 2) + side * 8;
            int x = bx + m;
            if (y < HH && x < WW) {
                size_t base = ((size_t)b * HW + (size_t)y * WW + x) * 64;
#pragma unroll
                for (int nt = 0; nt < 8; nt++) {
                    int oc0 = nt * 8 + (lane & 3) * 2;
                    float v0 = acc[nt][side * 2 + 0];
                    float v1 = acc[nt][side * 2 + 1];
                    __half h0 = __float2half_rn(v0);
                    __half h1 = __float2half_rn(v1);
                    __half2 hp; hp.x = h0; hp.y = h1;
                    __half2 lp;
                    lp.x = __float2half_rn(v0 - __half2float(h0));
                    lp.y = __float2half_rn(v1 - __half2float(h1));
                    *(__half2*)(out_hi + base + oc0) = hp;
                    *(__half2*)(out_lo + base + oc0) = lp;
                }
            }
        }
    } else {
        // heads: stage mid into smem, then 1x1 conv + bias -> NCHW fp32
        __syncthreads();   // mma/ldsm all done; safe to alias dynsmem
#pragma unroll
        for (int side = 0; side < 2; side++) {
            int m = (lane >> 2) + side * 8;
            int p = w * 16 + m;
#pragma unroll
            for (int nt = 0; nt < 8; nt++) {
                int oc0 = nt * 8 + (lane & 3) * 2;
                s_mid[p * 65 + oc0] = acc[nt][side * 2 + 0];
                s_mid[p * 65 + oc0 + 1] = acc[nt][side * 2 + 1];
            }
        }
        __syncthreads();
        if (tid < 128) {
            int p = tid;
            int yy = by + (p >> 4), xx = bx + (p & 15);
            if (yy < HH && xx < WW) {
                const float* row = s_mid + p * 65;
                float o[NOUT > 0 ? NOUT : 1];
#pragma unroll
                for (int n = 0; n < NOUT; n++) o[n] = s_b2[n];
#pragma unroll 8
                for (int c = 0; c < 64; c++) {
                    float a = row[c];
#pragma unroll
                    for (int n = 0; n < NOUT; n++) o[n] += a * s_w2[n * 64 + c];
                }
#pragma unroll
                for (int n = 0; n < NOUT; n++)
                    outf[((size_t)(b * NOUT + n) * HH + yy) * WW + xx] = o[n];
            }
        }
    }
}

// ===========================================================================
extern "C" void kernel_launch(void* const* d_in, const int* in_sizes, int n_in,
                              void* d_out, int out_size)
{
    const float* bev   = (const float*)d_in[0];
    const float* w_sh  = (const float*)d_in[1];
    const float* g_sh  = (const float*)d_in[2];
    const float* b_sh  = (const float*)d_in[3];
    const float* m_sh  = (const float*)d_in[4];
    const float* v_sh  = (const float*)d_in[5];
    const float* w_hm1 = (const float*)d_in[6];
    const float* g_hm1 = (const float*)d_in[7];
    const float* b_hm1 = (const float*)d_in[8];
    const float* m_hm1 = (const float*)d_in[9];
    const float* v_hm1 = (const float*)d_in[10];
    const float* w_hm2 = (const float*)d_in[11];
    const float* b_hm2 = (const float*)d_in[12];
    const float* w_rg1 = (const float*)d_in[13];
    const float* g_rg1 = (const float*)d_in[14];
    const float* b_rg1 = (const float*)d_in[15];
    const float* m_rg1 = (const float*)d_in[16];
    const float* v_rg1 = (const float*)d_in[17];
    const float* w_rg2 = (const float*)d_in[18];
    const float* b_rg2 = (const float*)d_in[19];

    __half *bev_hi, *bev_lo, *tr_hi, *tr_lo, *wi_sh, *wi_hm, *wi_rg;
    cudaGetSymbolAddress((void**)&bev_hi, g_bev_hi);
    cudaGetSymbolAddress((void**)&bev_lo, g_bev_lo);
    cudaGetSymbolAddress((void**)&tr_hi, g_tr_hi);
    cudaGetSymbolAddress((void**)&tr_lo, g_tr_lo);
    cudaGetSymbolAddress((void**)&wi_sh, g_wimg_sh);
    cudaGetSymbolAddress((void**)&wi_hm, g_wimg_hm);
    cudaGetSymbolAddress((void**)&wi_rg, g_wimg_rg);

    const int DSMEM = 18432 + 180 * 72 * 2 * 2;   // 70272 B
    cudaFuncSetAttribute(conv_mma_kernel<4, 0>, cudaFuncAttributeMaxDynamicSharedMemorySize, DSMEM);
    cudaFuncSetAttribute(conv_mma_kernel<1, 3>, cudaFuncAttributeMaxDynamicSharedMemorySize, DSMEM);
    cudaFuncSetAttribute(conv_mma_kernel<1, 8>, cudaFuncAttributeMaxDynamicSharedMemorySize, DSMEM);

    // 1. bev NCHW fp32 -> NHWC fp16 hi/lo
    nhwc_kernel<<<dim3(10, 8, BB * HH), 256>>>(bev);

    // 2. weight images
    prep_w_kernel<<<(64 * 256 * 9 + 255) / 256, 256>>>(w_sh, wi_sh, 256);
    prep_w_kernel<<<(64 * 64 * 9 + 255) / 256, 256>>>(w_hm1, wi_hm, 64);
    prep_w_kernel<<<(64 * 64 * 9 + 255) / 256, 256>>>(w_rg1, wi_rg, 64);

    dim3 grid(19, 38, BB);   // 16x8 pixel tiles

    // 3. trunk conv -> NHWC fp16 hi/lo
    conv_mma_kernel<4, 0><<<grid, 256, DSMEM>>>(
        bev_hi, bev_lo, wi_sh, g_sh, b_sh, m_sh, v_sh,
        nullptr, nullptr, tr_hi, tr_lo, nullptr);

    // 4. heads (fused 1x1 epilogue -> d_out)
    float* out = (float*)d_out;
    conv_mma_kernel<1, 3><<<grid, 256, DSMEM>>>(
        tr_hi, tr_lo, wi_hm, g_hm1, b_hm1, m_hm1, v_hm1,
        w_hm2, b_hm2, nullptr, nullptr, out);
    conv_mma_kernel<1, 8><<<grid, 256, DSMEM>>>(
        tr_hi, tr_lo, wi_rg, g_rg1, b_rg1, m_rg1, v_rg1,
        w_rg2, b_rg2, nullptr, nullptr, out + (size_t)BB * 3 * HW);
}

// round 9
// speedup vs baseline: 4.5012x; 1.3822x over previous
#include <cuda_runtime.h>
#include <cuda_fp16.h>
#include <cstdint>

#define EPSBN 1e-5f
#define HH 300
#define WW 300
#define HW 90000
#define BB 4

// ===========================================================================
// PTX helpers — baseline instructions only (target is sm_103 without 'a')
// ===========================================================================
__device__ __forceinline__ uint32_t smem_u32(const void* p) {
    uint32_t a;
    asm("{ .reg .u64 t; cvta.to.shared.u64 t, %1; cvt.u32.u64 %0, t; }"
        : "=r"(a) : "l"(p));
    return a;
}
__device__ __forceinline__ void ldsm4(uint32_t* r, uint32_t addr) {
    asm volatile("ldmatrix.sync.aligned.m8n8.x4.shared.b16 {%0,%1,%2,%3}, [%4];"
                 : "=r"(r[0]), "=r"(r[1]), "=r"(r[2]), "=r"(r[3]) : "r"(addr));
}
__device__ __forceinline__ void mma_f16(float* c, const uint32_t* a,
                                        uint32_t b0, uint32_t b1) {
    asm volatile(
        "mma.sync.aligned.m16n8k16.row.col.f32.f16.f16.f32 "
        "{%0,%1,%2,%3}, {%4,%5,%6,%7}, {%8,%9}, {%0,%1,%2,%3};"
        : "+f"(c[0]), "+f"(c[1]), "+f"(c[2]), "+f"(c[3])
        : "r"(a[0]), "r"(a[1]), "r"(a[2]), "r"(a[3]), "r"(b0), "r"(b1));
}
#define CP_ASYNC16(dst, src) \
    asm volatile("cp.async.cg.shared.global [%0], [%1], 16;" :: "r"(dst), "l"(src))
#define CP_COMMIT() asm volatile("cp.async.commit_group;" ::: "memory")
#define CP_WAIT1()  asm volatile("cp.async.wait_group 1;" ::: "memory")
#define CP_WAIT0()  asm volatile("cp.async.wait_group 0;" ::: "memory")

// ===========================================================================
// Device scratch (allocation-guard-safe)
// ===========================================================================
__device__ __half g_bev[(size_t)BB * HW * 256];
__device__ __half g_tr[(size_t)BB * HW * 64];
__device__ __half g_wimg_sh[36 * 4608];  // trunk: 4 cch x 9 shifts, [64 oc][72]
__device__ __half g_wimg_hm[9 * 4608];
__device__ __half g_wimg_rg[9 * 4608];

// ===========================================================================
// NCHW fp32 -> NHWC fp16 (bev)
// ===========================================================================
__global__ __launch_bounds__(256) void nhwc_kernel(const float* __restrict__ in)
{
    __shared__ float tile[32][33];
    const int tx = threadIdx.x & 31, ty = threadIdx.x >> 5;
    const int w0 = blockIdx.x * 32, c0 = blockIdx.y * 32;
    const int b = blockIdx.z / HH, h = blockIdx.z % HH;
#pragma unroll
    for (int q = 0; q < 4; q++) {
        int c = c0 + ty * 4 + q, w = w0 + tx;
        tile[ty * 4 + q][tx] = (w < WW) ? in[(((size_t)b * 256 + c) * HH + h) * WW + w] : 0.f;
    }
    __syncthreads();
#pragma unroll
    for (int q = 0; q < 4; q++) {
        int w = w0 + ty * 4 + q;
        if (w >= WW) continue;
        size_t o = ((size_t)b * HW + (size_t)h * WW + w) * 256 + c0 + tx;
        g_bev[o] = __float2half_rn(tile[tx][ty * 4 + q]);
    }
}

// ===========================================================================
// Weight prep: w[oc][ci][3][3] fp32 -> per (cchunk, shift) [64 oc][72] fp16
// ===========================================================================
__global__ void prep_w_kernel(const float* __restrict__ w,
                              __half* __restrict__ dst, int CIN)
{
    int i = blockIdx.x * 256 + threadIdx.x;
    if (i >= 64 * CIN * 9) return;
    int kk = i % 9;
    int ci = (i / 9) % CIN;
    int oc = i / (9 * CIN);
    int cc = ci >> 6, c = ci & 63;
    size_t base = (size_t)(cc * 9 + kk) * 4608;
    dst[base + oc * 72 + c] = __float2half_rn(w[i]);
}

// ===========================================================================
// Trunk: conv3x3 (256->64) + BN + ReLU, single-pass fp16 mma.
// CTA 256 thr (8 warps), tile 8 rows x 16 cols x 64 oc; warp = one row, M=16.
// ===========================================================================
__global__ __launch_bounds__(256, 2) void trunk_kernel(
    const __half* __restrict__ act, const __half* __restrict__ wimg,
    const float* __restrict__ gg, const float* __restrict__ bbp,
    const float* __restrict__ mm, const float* __restrict__ vv,
    __half* __restrict__ outp)
{
    extern __shared__ __align__(16) unsigned char dynsmem[];
    __half* sB = (__half*)dynsmem;                // 2 x 4608 (18432 B)
    __half* s_h = (__half*)(dynsmem + 18432);     // 180*72 (25920 B)

    __shared__ float s_scale[64], s_shift[64];

    const int tid = threadIdx.x;
    const int w = tid >> 5, lane = tid & 31;
    const int bx = blockIdx.x * 16, by = blockIdx.y * 8;
    const int b = blockIdx.z;

    if (tid < 64) {
        float sc = gg[tid] * rsqrtf(vv[tid] + EPSBN);
        s_scale[tid] = sc;
        s_shift[tid] = bbp[tid] - mm[tid] * sc;
    }

    const int mA = lane & 15;
    const int kselA = (lane >> 4) * 8;
    const int oclB = (lane & 7) + ((lane >> 4) & 1) * 8;
    const int koffB = (lane & 8) ? 8 : 0;

    const uint32_t sB_u = smem_u32(sB);
    const uint32_t sh_u = smem_u32(s_h);

    float acc[8][4];
#pragma unroll
    for (int i = 0; i < 8; i++)
#pragma unroll
        for (int j = 0; j < 4; j++) acc[i][j] = 0.f;

    {
        const char* src = (const char*)wimg;
        for (int i = tid; i < 576; i += 256)
            CP_ASYNC16(sB_u + i * 16, src + (size_t)i * 16);
        CP_COMMIT();
    }

    for (int cc = 0; cc < 4; cc++) {
        __syncthreads();
        // stage halo: 180 px x 64 ch = 8 uint4 (64 halves) per pixel
        for (int idx = tid; idx < 180 * 8; idx += 256) {
            int pix = idx >> 3, j = idx & 7;
            int r = pix / 18, col = pix % 18;
            int gy = by - 1 + r, gx = bx - 1 + col;
            uint4 v = make_uint4(0, 0, 0, 0);
            if ((unsigned)gy < HH && (unsigned)gx < WW)
                v = ((const uint4*)(act + ((size_t)b * HW + (size_t)gy * WW + gx) * 256 + cc * 64))[j];
            ((uint4*)(s_h + pix * 72))[j] = v;
        }

#pragma unroll 1
        for (int k = 0; k < 9; k++) {
            const int s = cc * 9 + k;
            const uint32_t cur = (uint32_t)(s & 1);
            if (s + 1 < 36) {
                const char* src = (const char*)(wimg + (size_t)(s + 1) * 4608);
                uint32_t dst = sB_u + (uint32_t)((s + 1) & 1) * 9216;
                for (int i = tid; i < 576; i += 256)
                    CP_ASYNC16(dst + i * 16, src + (size_t)i * 16);
                CP_COMMIT();
                CP_WAIT1();
            } else {
                CP_WAIT0();
            }
            __syncthreads();

            const int ky = k / 3, kx = k - 3 * ky;
            const uint32_t aBase = sh_u + (uint32_t)((((w + ky) * 18 + mA + kx) * 72 + kselA) * 2);
            const uint32_t bBase = sB_u + cur * 9216 + (uint32_t)((oclB * 72 + koffB) * 2);

#pragma unroll
            for (int kc = 0; kc < 4; kc++) {
                uint32_t a[4];
                ldsm4(a, aBase + kc * 32);
#pragma unroll
                for (int ng = 0; ng < 4; ng++) {
                    uint32_t bh[4];
                    ldsm4(bh, bBase + ng * 2304 + kc * 32);
                    mma_f16(acc[2 * ng + 0], a, bh[0], bh[1]);
                    mma_f16(acc[2 * ng + 1], a, bh[2], bh[3]);
                }
            }
            __syncthreads();
        }
    }

    // BN + ReLU -> NHWC fp16
    const int y = by + w;
#pragma unroll
    for (int side = 0; side < 2; side++) {
        int x = bx + (lane >> 2) + side * 8;
        if (y < HH && x < WW) {
            size_t base = ((size_t)b * HW + (size_t)y * WW + x) * 64;
#pragma unroll
            for (int nt = 0; nt < 8; nt++) {
                int oc0 = nt * 8 + (lane & 3) * 2;
                float v0 = fmaxf(acc[nt][side * 2 + 0] * s_scale[oc0] + s_shift[oc0], 0.f);
                float v1 = fmaxf(acc[nt][side * 2 + 1] * s_scale[oc0 + 1] + s_shift[oc0 + 1], 0.f);
                __half2 hp;
                hp.x = __float2half_rn(v0);
                hp.y = __float2half_rn(v1);
                *(__half2*)(outp + base + oc0) = hp;
            }
        }
    }
}

// ===========================================================================
// Fused heads: conv3x3 (64->64) x2 + BN + ReLU + 1x1(+bias) x2 -> d_out.
// Shares the halo (A) between both head convs; two B streams per shift.
// ===========================================================================
__global__ __launch_bounds__(256, 2) void heads_kernel(
    const __half* __restrict__ act,
    const __half* __restrict__ wimg_hm, const __half* __restrict__ wimg_rg,
    const float* __restrict__ g1, const float* __restrict__ b1,
    const float* __restrict__ m1, const float* __restrict__ v1,
    const float* __restrict__ g2, const float* __restrict__ b2,
    const float* __restrict__ m2, const float* __restrict__ v2,
    const float* __restrict__ w_hm2, const float* __restrict__ b_hm2,
    const float* __restrict__ w_rg2, const float* __restrict__ b_rg2,
    float* __restrict__ out)
{
    extern __shared__ __align__(16) unsigned char dynsmem[];
    __half* sB = (__half*)dynsmem;                // 2 bufs x 2 heads x 4608 (36864 B)
    __half* s_h = (__half*)(dynsmem + 36864);     // 180*72 (25920 B)
    float* s_mid = (float*)dynsmem;               // epilogue alias (128*65*4 B)

    __shared__ float s_sc1[64], s_sh1[64], s_sc2[64], s_sh2[64];
    __shared__ float s_w2h[3 * 64], s_w2r[8 * 64];
    __shared__ float s_b2h[3], s_b2r[8];

    const int tid = threadIdx.x;
    const int w = tid >> 5, lane = tid & 31;
    const int bx = blockIdx.x * 16, by = blockIdx.y * 8;
    const int b = blockIdx.z;

    if (tid < 64) {
        float sc = g1[tid] * rsqrtf(v1[tid] + EPSBN);
        s_sc1[tid] = sc;
        s_sh1[tid] = b1[tid] - m1[tid] * sc;
        float sc2 = g2[tid] * rsqrtf(v2[tid] + EPSBN);
        s_sc2[tid] = sc2;
        s_sh2[tid] = b2[tid] - m2[tid] * sc2;
    }
    for (int i = tid; i < 192; i += 256) s_w2h[i] = w_hm2[i];
    for (int i = tid; i < 512; i += 256) s_w2r[i] = w_rg2[i];
    if (tid < 3) s_b2h[tid] = b_hm2[tid];
    if (tid < 8) s_b2r[tid] = b_rg2[tid];

    const int mA = lane & 15;
    const int kselA = (lane >> 4) * 8;
    const int oclB = (lane & 7) + ((lane >> 4) & 1) * 8;
    const int koffB = (lane & 8) ? 8 : 0;

    const uint32_t sB_u = smem_u32(sB);
    const uint32_t sh_u = smem_u32(s_h);

    float accH[8][4], accR[8][4];
#pragma unroll
    for (int i = 0; i < 8; i++)
#pragma unroll
        for (int j = 0; j < 4; j++) { accH[i][j] = 0.f; accR[i][j] = 0.f; }

    // prefetch first shift's B images (hm + rg)
    {
        for (int i = tid; i < 576; i += 256) {
            CP_ASYNC16(sB_u + i * 16, (const char*)wimg_hm + (size_t)i * 16);
            CP_ASYNC16(sB_u + 9216 + i * 16, (const char*)wimg_rg + (size_t)i * 16);
        }
        CP_COMMIT();
    }

    // stage halo once (CIN = 64): 8 uint4 (64 halves) per pixel
    for (int idx = tid; idx < 180 * 8; idx += 256) {
        int pix = idx >> 3, j = idx & 7;
        int r = pix / 18, col = pix % 18;
        int gy = by - 1 + r, gx = bx - 1 + col;
        uint4 v = make_uint4(0, 0, 0, 0);
        if ((unsigned)gy < HH && (unsigned)gx < WW)
            v = ((const uint4*)(act + ((size_t)b * HW + (size_t)gy * WW + gx) * 64))[j];
        ((uint4*)(s_h + pix * 72))[j] = v;
    }

#pragma unroll 1
    for (int k = 0; k < 9; k++) {
        const uint32_t cur = (uint32_t)(k & 1);
        if (k + 1 < 9) {
            uint32_t dst = sB_u + (uint32_t)((k + 1) & 1) * 18432;
            for (int i = tid; i < 576; i += 256) {
                CP_ASYNC16(dst + i * 16, (const char*)(wimg_hm + (size_t)(k + 1) * 4608) + (size_t)i * 16);
                CP_ASYNC16(dst + 9216 + i * 16, (const char*)(wimg_rg + (size_t)(k + 1) * 4608) + (size_t)i * 16);
            }
            CP_COMMIT();
            CP_WAIT1();
        } else {
            CP_WAIT0();
        }
        __syncthreads();

        const int ky = k / 3, kx = k - 3 * ky;
        const uint32_t aBase = sh_u + (uint32_t)((((w + ky) * 18 + mA + kx) * 72 + kselA) * 2);
        const uint32_t bBaseH = sB_u + cur * 18432 + (uint32_t)((oclB * 72 + koffB) * 2);
        const uint32_t bBaseR = bBaseH + 9216;

#pragma unroll
        for (int kc = 0; kc < 4; kc++) {
            uint32_t a[4];
            ldsm4(a, aBase + kc * 32);
#pragma unroll
            for (int ng = 0; ng < 4; ng++) {
                uint32_t bh[4], br[4];
                ldsm4(bh, bBaseH + ng * 2304 + kc * 32);
                ldsm4(br, bBaseR + ng * 2304 + kc * 32);
                mma_f16(accH[2 * ng + 0], a, bh[0], bh[1]);
                mma_f16(accH[2 * ng + 1], a, bh[2], bh[3]);
                mma_f16(accR[2 * ng + 0], a, br[0], br[1]);
                mma_f16(accR[2 * ng + 1], a, br[2], br[3]);
            }
        }
        __syncthreads();
    }

    // ---- epilogue head 1 (heatmap, 3ch) ----
#pragma unroll
    for (int side = 0; side < 2; side++) {
        int p = w * 16 + (lane >> 2) + side * 8;
        int oc0 = (lane & 3) * 2;
#pragma unroll
        for (int nt = 0; nt < 8; nt++) {
            int oc = nt * 8 + oc0;
            s_mid[p * 65 + oc] = fmaxf(accH[nt][side * 2 + 0] * s_sc1[oc] + s_sh1[oc], 0.f);
            s_mid[p * 65 + oc + 1] = fmaxf(accH[nt][side * 2 + 1] * s_sc1[oc + 1] + s_sh1[oc + 1], 0.f);
        }
    }
    __syncthreads();
    if (tid < 128) {
        int p = tid;
        int yy = by + (p >> 4), xx = bx + (p & 15);
        if (yy < HH && xx < WW) {
            const float* row = s_mid + p * 65;
            float o0 = s_b2h[0], o1 = s_b2h[1], o2 = s_b2h[2];
#pragma unroll 8
            for (int c = 0; c < 64; c++) {
                float a = row[c];
                o0 += a * s_w2h[c];
                o1 += a * s_w2h[64 + c];
                o2 += a * s_w2h[128 + c];
            }
            size_t base = ((size_t)b * 3 * HH + yy) * WW + xx;
            out[base] = o0;
            out[base + (size_t)HW] = o1;
            out[base + (size_t)2 * HW] = o2;
        }
    }
    __syncthreads();

    // ---- epilogue head 2 (box_reg, 8ch) ----
#pragma unroll
    for (int side = 0; side < 2; side++) {
        int p = w * 16 + (lane >> 2) + side * 8;
        int oc0 = (lane & 3) * 2;
#pragma unroll
        for (int nt = 0; nt < 8; nt++) {
            int oc = nt * 8 + oc0;
            s_mid[p * 65 + oc] = fmaxf(accR[nt][side * 2 + 0] * s_sc2[oc] + s_sh2[oc], 0.f);
            s_mid[p * 65 + oc + 1] = fmaxf(accR[nt][side * 2 + 1] * s_sc2[oc + 1] + s_sh2[oc + 1], 0.f);
        }
    }
    __syncthreads();
    if (tid < 128) {
        int p = tid;
        int yy = by + (p >> 4), xx = bx + (p & 15);
        if (yy < HH && xx < WW) {
            const float* row = s_mid + p * 65;
            float o[8];
#pragma unroll
            for (int n = 0; n < 8; n++) o[n] = s_b2r[n];
#pragma unroll 8
            for (int c = 0; c < 64; c++) {
                float a = row[c];
#pragma unroll
                for (int n = 0; n < 8; n++) o[n] += a * s_w2r[n * 64 + c];
            }
            float* rg = out + (size_t)BB * 3 * HW;
#pragma unroll
            for (int n = 0; n < 8; n++)
                rg[((size_t)(b * 8 + n) * HH + yy) * WW + xx] = o[n];
        }
    }
}

// ===========================================================================
extern "C" void kernel_launch(void* const* d_in, const int* in_sizes, int n_in,
                              void* d_out, int out_size)
{
    const float* bev   = (const float*)d_in[0];
    const float* w_sh  = (const float*)d_in[1];
    const float* g_sh  = (const float*)d_in[2];
    const float* b_sh  = (const float*)d_in[3];
    const float* m_sh  = (const float*)d_in[4];
    const float* v_sh  = (const float*)d_in[5];
    const float* w_hm1 = (const float*)d_in[6];
    const float* g_hm1 = (const float*)d_in[7];
    const float* b_hm1 = (const float*)d_in[8];
    const float* m_hm1 = (const float*)d_in[9];
    const float* v_hm1 = (const float*)d_in[10];
    const float* w_hm2 = (const float*)d_in[11];
    const float* b_hm2 = (const float*)d_in[12];
    const float* w_rg1 = (const float*)d_in[13];
    const float* g_rg1 = (const float*)d_in[14];
    const float* b_rg1 = (const float*)d_in[15];
    const float* m_rg1 = (const float*)d_in[16];
    const float* v_rg1 = (const float*)d_in[17];
    const float* w_rg2 = (const float*)d_in[18];
    const float* b_rg2 = (const float*)d_in[19];

    __half *bevh, *trh, *wi_sh, *wi_hm, *wi_rg;
    cudaGetSymbolAddress((void**)&bevh, g_bev);
    cudaGetSymbolAddress((void**)&trh, g_tr);
    cudaGetSymbolAddress((void**)&wi_sh, g_wimg_sh);
    cudaGetSymbolAddress((void**)&wi_hm, g_wimg_hm);
    cudaGetSymbolAddress((void**)&wi_rg, g_wimg_rg);

    const int DSMEM_T = 18432 + 25920;   // 44352 B
    const int DSMEM_H = 36864 + 25920;   // 62784 B
    cudaFuncSetAttribute(trunk_kernel, cudaFuncAttributeMaxDynamicSharedMemorySize, DSMEM_T);
    cudaFuncSetAttribute(heads_kernel, cudaFuncAttributeMaxDynamicSharedMemorySize, DSMEM_H);

    // 1. bev NCHW fp32 -> NHWC fp16
    nhwc_kernel<<<dim3(10, 8, BB * HH), 256>>>(bev);

    // 2. weight images
    prep_w_kernel<<<(64 * 256 * 9 + 255) / 256, 256>>>(w_sh, wi_sh, 256);
    prep_w_kernel<<<(64 * 64 * 9 + 255) / 256, 256>>>(w_hm1, wi_hm, 64);
    prep_w_kernel<<<(64 * 64 * 9 + 255) / 256, 256>>>(w_rg1, wi_rg, 64);

    dim3 grid(19, 38, BB);   // 16x8 pixel tiles

    // 3. trunk conv -> NHWC fp16
    trunk_kernel<<<grid, 256, DSMEM_T>>>(bevh, wi_sh, g_sh, b_sh, m_sh, v_sh, trh);

    // 4. fused heads -> d_out
    heads_kernel<<<grid, 256, DSMEM_H>>>(
        trh, wi_hm, wi_rg,
        g_hm1, b_hm1, m_hm1, v_hm1,
        g_rg1, b_rg1, m_rg1, v_rg1,
        w_hm2, b_hm2, w_rg2, b_rg2, (float*)d_out);
}

// round 10
// speedup vs baseline: 5.2007x; 1.1554x over previous
#include <cuda_runtime.h>
#include <cuda_fp16.h>
#include <cstdint>

#define EPSBN 1e-5f
#define HH 300
#define WW 300
#define HW 90000
#define BB 4

// ===========================================================================
// PTX helpers — baseline instructions only (target is sm_103 without 'a')
// ===========================================================================
__device__ __forceinline__ uint32_t smem_u32(const void* p) {
    uint32_t a;
    asm("{ .reg .u64 t; cvta.to.shared.u64 t, %1; cvt.u32.u64 %0, t; }"
        : "=r"(a) : "l"(p));
    return a;
}
__device__ __forceinline__ void ldsm4(uint32_t* r, uint32_t addr) {
    asm volatile("ldmatrix.sync.aligned.m8n8.x4.shared.b16 {%0,%1,%2,%3}, [%4];"
                 : "=r"(r[0]), "=r"(r[1]), "=r"(r[2]), "=r"(r[3]) : "r"(addr));
}
__device__ __forceinline__ void mma_f16(float* c, const uint32_t* a,
                                        uint32_t b0, uint32_t b1) {
    asm volatile(
        "mma.sync.aligned.m16n8k16.row.col.f32.f16.f16.f32 "
        "{%0,%1,%2,%3}, {%4,%5,%6,%7}, {%8,%9}, {%0,%1,%2,%3};"
        : "+f"(c[0]), "+f"(c[1]), "+f"(c[2]), "+f"(c[3])
        : "r"(a[0]), "r"(a[1]), "r"(a[2]), "r"(a[3]), "r"(b0), "r"(b1));
}
#define CP_ASYNC16(dst, src) \
    asm volatile("cp.async.cg.shared.global [%0], [%1], 16;" :: "r"(dst), "l"(src))
#define CP_COMMIT() asm volatile("cp.async.commit_group;" ::: "memory")
#define CP_WAIT1()  asm volatile("cp.async.wait_group 1;" ::: "memory")
#define CP_WAIT0()  asm volatile("cp.async.wait_group 0;" ::: "memory")

// ===========================================================================
// Device scratch (allocation-guard-safe)
// ===========================================================================
__device__ __half g_bev[(size_t)BB * HW * 256];
__device__ __half g_tr[(size_t)BB * HW * 64];
__device__ __half g_wimg_sh[36 * 4608];  // trunk: 4 cch x 9 shifts, [64 oc][72]
__device__ __half g_wimg_hm[9 * 4608];
__device__ __half g_wimg_rg[9 * 4608];

// ===========================================================================
// NCHW fp32 -> NHWC fp16 (bev)
// ===========================================================================
__global__ __launch_bounds__(256) void nhwc_kernel(const float* __restrict__ in)
{
    __shared__ float tile[32][33];
    const int tx = threadIdx.x & 31, ty = threadIdx.x >> 5;
    const int w0 = blockIdx.x * 32, c0 = blockIdx.y * 32;
    const int b = blockIdx.z / HH, h = blockIdx.z % HH;
#pragma unroll
    for (int q = 0; q < 4; q++) {
        int c = c0 + ty * 4 + q, w = w0 + tx;
        tile[ty * 4 + q][tx] = (w < WW) ? in[(((size_t)b * 256 + c) * HH + h) * WW + w] : 0.f;
    }
    __syncthreads();
#pragma unroll
    for (int q = 0; q < 4; q++) {
        int w = w0 + ty * 4 + q;
        if (w >= WW) continue;
        size_t o = ((size_t)b * HW + (size_t)h * WW + w) * 256 + c0 + tx;
        g_bev[o] = __float2half_rn(tile[tx][ty * 4 + q]);
    }
}

// ===========================================================================
// Weight prep: w[oc][ci][3][3] fp32 -> per (cchunk, shift) [64 oc][72] fp16
// ===========================================================================
__global__ void prep_w_kernel(const float* __restrict__ w,
                              __half* __restrict__ dst, int CIN)
{
    int i = blockIdx.x * 256 + threadIdx.x;
    if (i >= 64 * CIN * 9) return;
    int kk = i % 9;
    int ci = (i / 9) % CIN;
    int oc = i / (9 * CIN);
    int cc = ci >> 6, c = ci & 63;
    size_t base = (size_t)(cc * 9 + kk) * 4608;
    dst[base + oc * 72 + c] = __float2half_rn(w[i]);
}

// ===========================================================================
// Trunk: conv3x3 (256->64) + BN + ReLU, single-pass fp16 mma, M=32/warp.
// CTA 256 thr (8 warps), tile 16x16 px x 64 oc; warp w = rows 2w, 2w+1.
// Triple-buffered B, one __syncthreads per shift.
// ===========================================================================
__global__ __launch_bounds__(256, 2) void trunk_kernel(
    const __half* __restrict__ act, const __half* __restrict__ wimg,
    const float* __restrict__ gg, const float* __restrict__ bbp,
    const float* __restrict__ mm, const float* __restrict__ vv,
    __half* __restrict__ outp)
{
    extern __shared__ __align__(16) unsigned char dynsmem[];
    __half* sB = (__half*)dynsmem;                // 3 x 4608 elems (27648 B)
    __half* s_h = (__half*)(dynsmem + 27648);     // 324 px x 72 (46656 B)

    __shared__ float s_scale[64], s_shift[64];

    const int tid = threadIdx.x;
    const int w = tid >> 5, lane = tid & 31;
    const int bx = blockIdx.x * 16, by = blockIdx.y * 16;
    const int b = blockIdx.z;

    if (tid < 64) {
        float sc = gg[tid] * rsqrtf(vv[tid] + EPSBN);
        s_scale[tid] = sc;
        s_shift[tid] = bbp[tid] - mm[tid] * sc;
    }

    const int mA = lane & 15;
    const int kselA = (lane >> 4) * 8;
    const int oclB = (lane & 7) + ((lane >> 4) & 1) * 8;
    const int koffB = (lane & 8) ? 8 : 0;

    const uint32_t sB_u = smem_u32(sB);
    const uint32_t sh_u = smem_u32(s_h);

    float acc0[8][4], acc1[8][4];
#pragma unroll
    for (int i = 0; i < 8; i++)
#pragma unroll
        for (int j = 0; j < 4; j++) { acc0[i][j] = 0.f; acc1[i][j] = 0.f; }

    // prefetch B images for s=0, s=1 (two groups)
    for (int i = tid; i < 576; i += 256)
        CP_ASYNC16(sB_u + i * 16, (const char*)wimg + (size_t)i * 16);
    CP_COMMIT();
    for (int i = tid; i < 576; i += 256)
        CP_ASYNC16(sB_u + 9216 + i * 16, (const char*)(wimg + 4608) + (size_t)i * 16);
    CP_COMMIT();

    for (int cc = 0; cc < 4; cc++) {
        __syncthreads();   // all warps done reading previous halo
        // stage halo: 324 px (18x18) x 64 ch, 8 uint4 per pixel, pitch 72
        for (int idx = tid; idx < 324 * 8; idx += 256) {
            int pix = idx >> 3, j = idx & 7;
            int r = pix / 18, col = pix % 18;
            int gy = by - 1 + r, gx = bx - 1 + col;
            uint4 v = make_uint4(0, 0, 0, 0);
            if ((unsigned)gy < HH && (unsigned)gx < WW)
                v = ((const uint4*)(act + ((size_t)b * HW + (size_t)gy * WW + gx) * 256 + cc * 64))[j];
            ((uint4*)(s_h + pix * 72))[j] = v;
        }

#pragma unroll 1
        for (int k = 0; k < 9; k++) {
            const int s = cc * 9 + k;
            if (s + 1 < 36) CP_WAIT1(); else CP_WAIT0();
            __syncthreads();   // cp data + halo visible; readers of buf (s+2)%3 done
            if (s + 2 < 36) {
                const char* src = (const char*)(wimg + (size_t)(s + 2) * 4608);
                uint32_t dst = sB_u + (uint32_t)((s + 2) % 3) * 9216;
                for (int i = tid; i < 576; i += 256)
                    CP_ASYNC16(dst + i * 16, src + (size_t)i * 16);
                CP_COMMIT();
            }

            const int ky = k / 3, kx = k - 3 * ky;
            const uint32_t aBase = sh_u +
                (uint32_t)((((2 * w + ky) * 18 + mA + kx) * 72 + kselA) * 2);
            const uint32_t bBase = sB_u + (uint32_t)(s % 3) * 9216 +
                (uint32_t)((oclB * 72 + koffB) * 2);

#pragma unroll
            for (int kc = 0; kc < 4; kc++) {
                uint32_t a0[4], a1[4];
                ldsm4(a0, aBase + kc * 32);
                ldsm4(a1, aBase + 2592 + kc * 32);   // next row: +18*72*2 B
#pragma unroll
                for (int ng = 0; ng < 4; ng++) {
                    uint32_t bh[4];
                    ldsm4(bh, bBase + ng * 2304 + kc * 32);
                    mma_f16(acc0[2 * ng + 0], a0, bh[0], bh[1]);
                    mma_f16(acc0[2 * ng + 1], a0, bh[2], bh[3]);
                    mma_f16(acc1[2 * ng + 0], a1, bh[0], bh[1]);
                    mma_f16(acc1[2 * ng + 1], a1, bh[2], bh[3]);
                }
            }
        }
    }

    // BN + ReLU -> NHWC fp16 (2 rows per warp)
#pragma unroll
    for (int rr = 0; rr < 2; rr++) {
        const int y = by + 2 * w + rr;
#pragma unroll
        for (int side = 0; side < 2; side++) {
            int x = bx + (lane >> 2) + side * 8;
            if (y < HH && x < WW) {
                size_t base = ((size_t)b * HW + (size_t)y * WW + x) * 64;
#pragma unroll
                for (int nt = 0; nt < 8; nt++) {
                    int oc0 = nt * 8 + (lane & 3) * 2;
                    float v0 = (rr == 0) ? acc0[nt][side * 2 + 0] : acc1[nt][side * 2 + 0];
                    float v1 = (rr == 0) ? acc0[nt][side * 2 + 1] : acc1[nt][side * 2 + 1];
                    v0 = fmaxf(v0 * s_scale[oc0] + s_shift[oc0], 0.f);
                    v1 = fmaxf(v1 * s_scale[oc0 + 1] + s_shift[oc0 + 1], 0.f);
                    __half2 hp;
                    hp.x = __float2half_rn(v0);
                    hp.y = __float2half_rn(v1);
                    *(__half2*)(outp + base + oc0) = hp;
                }
            }
        }
    }
}

// ===========================================================================
// Fused heads: conv3x3 (64->64) x2 + BN + ReLU + 1x1(+bias) x2 -> d_out.
// M=32/warp, shared A for both heads; triple-buffered dual B streams.
// ===========================================================================
__global__ __launch_bounds__(256, 1) void heads_kernel(
    const __half* __restrict__ act,
    const __half* __restrict__ wimg_hm, const __half* __restrict__ wimg_rg,
    const float* __restrict__ g1, const float* __restrict__ b1,
    const float* __restrict__ m1, const float* __restrict__ v1,
    const float* __restrict__ g2, const float* __restrict__ b2,
    const float* __restrict__ m2, const float* __restrict__ v2,
    const float* __restrict__ w_hm2, const float* __restrict__ b_hm2,
    const float* __restrict__ w_rg2, const float* __restrict__ b_rg2,
    float* __restrict__ out)
{
    extern __shared__ __align__(16) unsigned char dynsmem[];
    __half* sB = (__half*)dynsmem;                // 3 bufs x (hm|rg 9216B) = 55296 B
    __half* s_h = (__half*)(dynsmem + 55296);     // 324 x 72 (46656 B)
    float* s_mid = (float*)dynsmem;               // epilogue alias: 256*65*4 = 66560 B

    __shared__ float s_sc1[64], s_sh1[64], s_sc2[64], s_sh2[64];
    __shared__ float s_w2h[3 * 64], s_w2r[8 * 64];
    __shared__ float s_b2h[3], s_b2r[8];

    const int tid = threadIdx.x;
    const int w = tid >> 5, lane = tid & 31;
    const int bx = blockIdx.x * 16, by = blockIdx.y * 16;
    const int b = blockIdx.z;

    if (tid < 64) {
        float sc = g1[tid] * rsqrtf(v1[tid] + EPSBN);
        s_sc1[tid] = sc;
        s_sh1[tid] = b1[tid] - m1[tid] * sc;
        float sc2 = g2[tid] * rsqrtf(v2[tid] + EPSBN);
        s_sc2[tid] = sc2;
        s_sh2[tid] = b2[tid] - m2[tid] * sc2;
    }
    for (int i = tid; i < 192; i += 256) s_w2h[i] = w_hm2[i];
    for (int i = tid; i < 512; i += 256) s_w2r[i] = w_rg2[i];
    if (tid < 3) s_b2h[tid] = b_hm2[tid];
    if (tid < 8) s_b2r[tid] = b_rg2[tid];

    const int mA = lane & 15;
    const int kselA = (lane >> 4) * 8;
    const int oclB = (lane & 7) + ((lane >> 4) & 1) * 8;
    const int koffB = (lane & 8) ? 8 : 0;

    const uint32_t sB_u = smem_u32(sB);
    const uint32_t sh_u = smem_u32(s_h);

    float aH0[8][4], aH1[8][4], aR0[8][4], aR1[8][4];
#pragma unroll
    for (int i = 0; i < 8; i++)
#pragma unroll
        for (int j = 0; j < 4; j++) {
            aH0[i][j] = 0.f; aH1[i][j] = 0.f;
            aR0[i][j] = 0.f; aR1[i][j] = 0.f;
        }

    // prefetch shifts 0 and 1 (two groups, each hm+rg)
    for (int i = tid; i < 576; i += 256) {
        CP_ASYNC16(sB_u + i * 16, (const char*)wimg_hm + (size_t)i * 16);
        CP_ASYNC16(sB_u + 4608 * 2 + i * 16, (const char*)wimg_rg + (size_t)i * 16);
    }
    CP_COMMIT();
    for (int i = tid; i < 576; i += 256) {
        CP_ASYNC16(sB_u + 18432 + i * 16, (const char*)(wimg_hm + 4608) + (size_t)i * 16);
        CP_ASYNC16(sB_u + 18432 + 9216 + i * 16, (const char*)(wimg_rg + 4608) + (size_t)i * 16);
    }
    CP_COMMIT();

    // stage halo once (CIN = 64): 324 px, 8 uint4 per pixel
    for (int idx = tid; idx < 324 * 8; idx += 256) {
        int pix = idx >> 3, j = idx & 7;
        int r = pix / 18, col = pix % 18;
        int gy = by - 1 + r, gx = bx - 1 + col;
        uint4 v = make_uint4(0, 0, 0, 0);
        if ((unsigned)gy < HH && (unsigned)gx < WW)
            v = ((const uint4*)(act + ((size_t)b * HW + (size_t)gy * WW + gx) * 64))[j];
        ((uint4*)(s_h + pix * 72))[j] = v;
    }

#pragma unroll 1
    for (int k = 0; k < 9; k++) {
        if (k + 1 < 9) CP_WAIT1(); else CP_WAIT0();
        __syncthreads();
        if (k + 2 < 9) {
            uint32_t dst = sB_u + (uint32_t)((k + 2) % 3) * 18432;
            for (int i = tid; i < 576; i += 256) {
                CP_ASYNC16(dst + i * 16, (const char*)(wimg_hm + (size_t)(k + 2) * 4608) + (size_t)i * 16);
                CP_ASYNC16(dst + 9216 + i * 16, (const char*)(wimg_rg + (size_t)(k + 2) * 4608) + (size_t)i * 16);
            }
            CP_COMMIT();
        }

        const int ky = k / 3, kx = k - 3 * ky;
        const uint32_t aBase = sh_u +
            (uint32_t)((((2 * w + ky) * 18 + mA + kx) * 72 + kselA) * 2);
        const uint32_t bBaseH = sB_u + (uint32_t)(k % 3) * 18432 +
            (uint32_t)((oclB * 72 + koffB) * 2);
        const uint32_t bBaseR = bBaseH + 9216;

#pragma unroll
        for (int kc = 0; kc < 4; kc++) {
            uint32_t a0[4], a1[4];
            ldsm4(a0, aBase + kc * 32);
            ldsm4(a1, aBase + 2592 + kc * 32);
#pragma unroll
            for (int ng = 0; ng < 4; ng++) {
                uint32_t bh[4], br[4];
                ldsm4(bh, bBaseH + ng * 2304 + kc * 32);
                ldsm4(br, bBaseR + ng * 2304 + kc * 32);
                mma_f16(aH0[2 * ng + 0], a0, bh[0], bh[1]);
                mma_f16(aH0[2 * ng + 1], a0, bh[2], bh[3]);
                mma_f16(aH1[2 * ng + 0], a1, bh[0], bh[1]);
                mma_f16(aH1[2 * ng + 1], a1, bh[2], bh[3]);
                mma_f16(aR0[2 * ng + 0], a0, br[0], br[1]);
                mma_f16(aR0[2 * ng + 1], a0, br[2], br[3]);
                mma_f16(aR1[2 * ng + 0], a1, br[0], br[1]);
                mma_f16(aR1[2 * ng + 1], a1, br[2], br[3]);
            }
        }
    }
    __syncthreads();   // mma/ldsm done; safe to alias dynsmem as s_mid

    // ---- epilogue head 1 (heatmap, 3ch) ----
#pragma unroll
    for (int rr = 0; rr < 2; rr++)
#pragma unroll
        for (int side = 0; side < 2; side++) {
            int p = (2 * w + rr) * 16 + (lane >> 2) + side * 8;
            int oc0 = (lane & 3) * 2;
#pragma unroll
            for (int nt = 0; nt < 8; nt++) {
                int oc = nt * 8 + oc0;
                float v0 = (rr == 0) ? aH0[nt][side * 2 + 0] : aH1[nt][side * 2 + 0];
                float v1 = (rr == 0) ? aH0[nt][side * 2 + 1] : aH1[nt][side * 2 + 1];
                s_mid[p * 65 + oc] = fmaxf(v0 * s_sc1[oc] + s_sh1[oc], 0.f);
                s_mid[p * 65 + oc + 1] = fmaxf(v1 * s_sc1[oc + 1] + s_sh1[oc + 1], 0.f);
            }
        }
    __syncthreads();
    {
        int p = tid;
        int yy = by + (p >> 4), xx = bx + (p & 15);
        if (yy < HH && xx < WW) {
            const float* row = s_mid + p * 65;
            float o0 = s_b2h[0], o1 = s_b2h[1], o2 = s_b2h[2];
#pragma unroll 8
            for (int c = 0; c < 64; c++) {
                float a = row[c];
                o0 += a * s_w2h[c];
                o1 += a * s_w2h[64 + c];
                o2 += a * s_w2h[128 + c];
            }
            size_t base = ((size_t)b * 3 * HH + yy) * WW + xx;
            out[base] = o0;
            out[base + (size_t)HW] = o1;
            out[base + (size_t)2 * HW] = o2;
        }
    }
    __syncthreads();

    // ---- epilogue head 2 (box_reg, 8ch) ----
#pragma unroll
    for (int rr = 0; rr < 2; rr++)
#pragma unroll
        for (int side = 0; side < 2; side++) {
            int p = (2 * w + rr) * 16 + (lane >> 2) + side * 8;
            int oc0 = (lane & 3) * 2;
#pragma unroll
            for (int nt = 0; nt < 8; nt++) {
                int oc = nt * 8 + oc0;
                float v0 = (rr == 0) ? aR0[nt][side * 2 + 0] : aR1[nt][side * 2 + 0];
                float v1 = (rr == 0) ? aR0[nt][side * 2 + 1] : aR1[nt][side * 2 + 1];
                s_mid[p * 65 + oc] = fmaxf(v0 * s_sc2[oc] + s_sh2[oc], 0.f);
                s_mid[p * 65 + oc + 1] = fmaxf(v1 * s_sc2[oc + 1] + s_sh2[oc + 1], 0.f);
            }
        }
    __syncthreads();
    {
        int p = tid;
        int yy = by + (p >> 4), xx = bx + (p & 15);
        if (yy < HH && xx < WW) {
            const float* row = s_mid + p * 65;
            float o[8];
#pragma unroll
            for (int n = 0; n < 8; n++) o[n] = s_b2r[n];
#pragma unroll 8
            for (int c = 0; c < 64; c++) {
                float a = row[c];
#pragma unroll
                for (int n = 0; n < 8; n++) o[n] += a * s_w2r[n * 64 + c];
            }
            float* rg = out + (size_t)BB * 3 * HW;
#pragma unroll
            for (int n = 0; n < 8; n++)
                rg[((size_t)(b * 8 + n) * HH + yy) * WW + xx] = o[n];
        }
    }
}

// ===========================================================================
extern "C" void kernel_launch(void* const* d_in, const int* in_sizes, int n_in,
                              void* d_out, int out_size)
{
    const float* bev   = (const float*)d_in[0];
    const float* w_sh  = (const float*)d_in[1];
    const float* g_sh  = (const float*)d_in[2];
    const float* b_sh  = (const float*)d_in[3];
    const float* m_sh  = (const float*)d_in[4];
    const float* v_sh  = (const float*)d_in[5];
    const float* w_hm1 = (const float*)d_in[6];
    const float* g_hm1 = (const float*)d_in[7];
    const float* b_hm1 = (const float*)d_in[8];
    const float* m_hm1 = (const float*)d_in[9];
    const float* v_hm1 = (const float*)d_in[10];
    const float* w_hm2 = (const float*)d_in[11];
    const float* b_hm2 = (const float*)d_in[12];
    const float* w_rg1 = (const float*)d_in[13];
    const float* g_rg1 = (const float*)d_in[14];
    const float* b_rg1 = (const float*)d_in[15];
    const float* m_rg1 = (const float*)d_in[16];
    const float* v_rg1 = (const float*)d_in[17];
    const float* w_rg2 = (const float*)d_in[18];
    const float* b_rg2 = (const float*)d_in[19];

    __half *bevh, *trh, *wi_sh, *wi_hm, *wi_rg;
    cudaGetSymbolAddress((void**)&bevh, g_bev);
    cudaGetSymbolAddress((void**)&trh, g_tr);
    cudaGetSymbolAddress((void**)&wi_sh, g_wimg_sh);
    cudaGetSymbolAddress((void**)&wi_hm, g_wimg_hm);
    cudaGetSymbolAddress((void**)&wi_rg, g_wimg_rg);

    const int DSMEM_T = 27648 + 46656;   // 74304 B
    const int DSMEM_H = 55296 + 46656;   // 101952 B
    cudaFuncSetAttribute(trunk_kernel, cudaFuncAttributeMaxDynamicSharedMemorySize, DSMEM_T);
    cudaFuncSetAttribute(heads_kernel, cudaFuncAttributeMaxDynamicSharedMemorySize, DSMEM_H);

    // 1. bev NCHW fp32 -> NHWC fp16
    nhwc_kernel<<<dim3(10, 8, BB * HH), 256>>>(bev);

    // 2. weight images
    prep_w_kernel<<<(64 * 256 * 9 + 255) / 256, 256>>>(w_sh, wi_sh, 256);
    prep_w_kernel<<<(64 * 64 * 9 + 255) / 256, 256>>>(w_hm1, wi_hm, 64);
    prep_w_kernel<<<(64 * 64 * 9 + 255) / 256, 256>>>(w_rg1, wi_rg, 64);

    dim3 grid(19, 19, BB);   // 16x16 pixel tiles

    // 3. trunk conv -> NHWC fp16
    trunk_kernel<<<grid, 256, DSMEM_T>>>(bevh, wi_sh, g_sh, b_sh, m_sh, v_sh, trh);

    // 4. fused heads -> d_out
    heads_kernel<<<grid, 256, DSMEM_H>>>(
        trh, wi_hm, wi_rg,
        g_hm1, b_hm1, m_hm1, v_hm1,
        g_rg1, b_rg1, m_rg1, v_rg1,
        w_hm2, b_hm2, w_rg2, b_rg2, (float*)d_out);
}